// round 2
// baseline (speedup 1.0000x reference)
#include <cuda_runtime.h>

// channel_attention collapses to: out = LN_c(Wp @ x + bp)*gp + betap + x
// (softmax row-sum == 1 makes the whole q/k/attention branch an identity).
//
// x [BO=1024][C=128][S=400] fp32. Per block: one (b,o) and an 80-wide s tile.
// GEMM M=128, N=80, K=128 with packed fma.rn.f32x2; packed dim = j so the
// A operand (W columns) loads as native 64-bit pairs (no MOV packing) and the
// B operand (x) is pre-duplicated {x,x} in smem and fetched 2-ops-per-LDS.128.

#define C        128
#define S        400
#define TS       80
#define NTILE    (S / TS)         // 5
#define THREADS  256
#define XD_PITCH (2 * TS)         // 160 floats per duplicated row

typedef unsigned long long ull;

__device__ float Wt_g[C * C];     // Wt_g[k*C + j] = Wp[j*C + k]

__device__ __forceinline__ void fma2(ull& d, ull a, ull b) {
    asm("fma.rn.f32x2 %0, %1, %2, %0;" : "+l"(d) : "l"(a), "l"(b));
}
__device__ __forceinline__ float2 up2(ull v) {
    float2 r;
    asm("mov.b64 {%0,%1}, %2;" : "=f"(r.x), "=f"(r.y) : "l"(v));
    return r;
}

__global__ void wt_kernel(const float* __restrict__ Wp) {
    int idx = blockIdx.x * 256 + threadIdx.x;   // coalesced read of Wp[j][k]
    int j = idx >> 7, k = idx & 127;
    Wt_g[k * C + j] = Wp[idx];
}

extern __shared__ float s_mem[];

__global__ __launch_bounds__(THREADS, 1)
void ca_kernel(const float* __restrict__ x,
               const float* __restrict__ bp,
               const float* __restrict__ gp,
               const float* __restrict__ betap,
               float* __restrict__ out) {
    float* Wt   = s_mem;                    // [128][128]   Wt[k][j]
    float* Xd   = Wt + C * C;               // [128][160]   {x,x} duplicated
    float* s_bp = Xd + C * XD_PITCH;        // [128]
    float* s_gp = s_bp + C;
    float* s_bt = s_gp + C;

    const int tid  = threadIdx.x;
    const int bo   = blockIdx.x / NTILE;
    const int tile = blockIdx.x % NTILE;
    const float* xb = x   + (size_t)bo * C * S + tile * TS;
    float*       ob = out + (size_t)bo * C * S + tile * TS;

    // ---- smem fill (all coalesced / conflict-free) ----
    {
        const float4* src = (const float4*)Wt_g;
        float4* dst = (float4*)Wt;
        #pragma unroll 4
        for (int i = tid; i < C * C / 4; i += THREADS) dst[i] = src[i];
    }
    if (tid < C) {
        s_bp[tid] = bp[tid];
        s_gp[tid] = gp[tid];
        s_bt[tid] = betap[tid];
    }
    #pragma unroll 5
    for (int t = tid; t < C * (TS / 4); t += THREADS) {
        int c = t / (TS / 4);
        int q = t % (TS / 4);
        float4 v = *(const float4*)(xb + (size_t)c * S + q * 4);
        float4* dst = (float4*)(Xd + c * XD_PITCH + q * 8);
        dst[0] = make_float4(v.x, v.x, v.y, v.y);
        dst[1] = make_float4(v.z, v.z, v.w, v.w);
    }
    __syncthreads();

    // ---- main loop: lane tj owns j=4tj..4tj+3 (2 packed pairs),
    //      warp ts owns s columns sb..sb+9 ----
    const int tj = tid & 31;
    const int ts = tid >> 5;
    const int sb = ts * 10;

    ull acc[2][10];
    #pragma unroll
    for (int m = 0; m < 2; m++)
        #pragma unroll
        for (int n = 0; n < 10; n++) acc[m][n] = 0ull;

    const float* wrow = Wt + tj * 4;        // + k*128 per step
    const float* xrow = Xd + sb * 2;        // + k*160 per step

    #pragma unroll 2
    for (int k = 0; k < C; k++) {
        ulonglong2 a2 = *(const ulonglong2*)(wrow + k * C);       // {w0,w1},{w2,w3}
        const ulonglong2* bq = (const ulonglong2*)(xrow + k * XD_PITCH);
        ulonglong2 b0 = bq[0], b1 = bq[1], b2 = bq[2], b3 = bq[3], b4 = bq[4];

        fma2(acc[0][0], a2.x, b0.x); fma2(acc[0][1], a2.x, b0.y);
        fma2(acc[0][2], a2.x, b1.x); fma2(acc[0][3], a2.x, b1.y);
        fma2(acc[0][4], a2.x, b2.x); fma2(acc[0][5], a2.x, b2.y);
        fma2(acc[0][6], a2.x, b3.x); fma2(acc[0][7], a2.x, b3.y);
        fma2(acc[0][8], a2.x, b4.x); fma2(acc[0][9], a2.x, b4.y);

        fma2(acc[1][0], a2.y, b0.x); fma2(acc[1][1], a2.y, b0.y);
        fma2(acc[1][2], a2.y, b1.x); fma2(acc[1][3], a2.y, b1.y);
        fma2(acc[1][4], a2.y, b2.x); fma2(acc[1][5], a2.y, b2.y);
        fma2(acc[1][6], a2.y, b3.x); fma2(acc[1][7], a2.y, b3.y);
        fma2(acc[1][8], a2.y, b4.x); fma2(acc[1][9], a2.y, b4.y);
    }

    // ---- epilogue: +bp, LayerNorm over j (intra-warp shfl), affine, +x ----
    const int j0 = tj * 4;
    float b0 = s_bp[j0], b1 = s_bp[j0 + 1], b2 = s_bp[j0 + 2], b3 = s_bp[j0 + 3];

    float y[4][10];
    #pragma unroll
    for (int n = 0; n < 10; n++) {
        float2 p0 = up2(acc[0][n]);
        float2 p1 = up2(acc[1][n]);
        y[0][n] = p0.x + b0;
        y[1][n] = p0.y + b1;
        y[2][n] = p1.x + b2;
        y[3][n] = p1.y + b3;
    }

    float mu[10], rs[10];
    #pragma unroll
    for (int n = 0; n < 10; n++) {
        float sv = 0.f, sq = 0.f;
        #pragma unroll
        for (int m = 0; m < 4; m++) {
            float v = y[m][n];
            sv += v;
            sq = fmaf(v, v, sq);
        }
        #pragma unroll
        for (int off = 16; off > 0; off >>= 1) {
            sv += __shfl_xor_sync(0xffffffffu, sv, off);
            sq += __shfl_xor_sync(0xffffffffu, sq, off);
        }
        float m_  = sv * (1.0f / 128.0f);
        float var = sq * (1.0f / 128.0f) - m_ * m_;
        mu[n] = m_;
        rs[n] = rsqrtf(var + 1e-5f);
    }

    #pragma unroll
    for (int m = 0; m < 4; m++) {
        int j = j0 + m;
        float g = s_gp[j];
        float bb = s_bt[j];
        const float* xd = Xd + j * XD_PITCH + sb * 2;   // duplicated: x at 2*n
        float* orow = ob + (size_t)j * S + sb;
        #pragma unroll
        for (int n = 0; n < 5; n++) {
            float2 o;
            o.x = (y[m][2*n]   - mu[2*n])   * rs[2*n]   * g + bb + xd[4*n];
            o.y = (y[m][2*n+1] - mu[2*n+1]) * rs[2*n+1] * g + bb + xd[4*n + 2];
            *(float2*)(orow + 2 * n) = o;
        }
    }
}

extern "C" void kernel_launch(void* const* d_in, const int* in_sizes, int n_in,
                              void* d_out, int out_size) {
    // metadata order: x, Wq, bq, gq, betaq, Wk, bk, gk, betak, Wp, bp, gp, betap
    const float* x     = (const float*)d_in[0];
    const float* Wp    = (const float*)d_in[9];
    const float* bp    = (const float*)d_in[10];
    const float* gp    = (const float*)d_in[11];
    const float* betap = (const float*)d_in[12];
    float* out = (float*)d_out;

    const int BO = in_sizes[0] / (C * S);   // 1024
    const size_t smem =
        (size_t)(C * C + C * XD_PITCH + 3 * C) * sizeof(float);

    cudaFuncSetAttribute(ca_kernel,
                         cudaFuncAttributeMaxDynamicSharedMemorySize,
                         (int)smem);

    wt_kernel<<<C * C / 256, 256>>>(Wp);
    ca_kernel<<<BO * NTILE, THREADS, smem>>>(x, bp, gp, betap, out);
}

// round 3
// speedup vs baseline: 1.7152x; 1.7152x over previous
#include <cuda_runtime.h>

// channel_attention collapses to: out = LN_c(Wp @ x + bp)*gp + betap + x
// (softmax row-sum == 1 makes the q/k/attention branch an identity).
//
// x [BO=1024][C=128][S=400] fp32. Block = one (b,o) x 80-wide s tile.
// GEMM M=128, N=80, K=128 via fma.rn.f32x2, s-packed accumulators:
//   - B operand: natural {x_s,x_s+1} LDS.64 pairs from plain (un-duplicated) X
//   - A operand: 4 W values/lane, duplicated {w,w} in registers (4 MOVs/k)
//   - half-warp j-duplication: lanes 0-15 / 16-31 share W reads (2 phases),
//     own different s-groups -> crossbar demand 7 phases per 10 fma-cycles.
// smem ~109 KB -> 2 blocks/SM.

#define C        128
#define S        400
#define TS       80
#define NTILE    (S / TS)          // 5
#define THREADS  256
#define XP       84                // X pitch in floats (16B-aligned rows)

typedef unsigned long long ull;

__device__ float Wt_g[C * C];      // Wt_g[k*C + j] = Wp[j*C + k]

__device__ __forceinline__ ull pk2(float lo, float hi) {
    ull r;
    asm("mov.b64 %0, {%1,%2};" : "=l"(r) : "f"(lo), "f"(hi));
    return r;
}
__device__ __forceinline__ void fma2(ull& d, ull a, ull b) {
    asm("fma.rn.f32x2 %0, %1, %2, %0;" : "+l"(d) : "l"(a), "l"(b));
}
__device__ __forceinline__ float2 up2(ull v) {
    float2 r;
    asm("mov.b64 {%0,%1}, %2;" : "=f"(r.x), "=f"(r.y) : "l"(v));
    return r;
}

__global__ void wt_kernel(const float* __restrict__ Wp) {
    int idx = blockIdx.x * 256 + threadIdx.x;   // coalesced read of Wp[j][k]
    int j = idx >> 7, k = idx & 127;
    Wt_g[k * C + j] = Wp[idx];
}

extern __shared__ float s_mem[];

__global__ __launch_bounds__(THREADS, 2)
void ca_kernel(const float* __restrict__ x,
               const float* __restrict__ bp,
               const float* __restrict__ gp,
               const float* __restrict__ betap,
               float* __restrict__ out) {
    float*  Wt   = s_mem;                   // [128][128]  Wt[k][j]
    float*  X    = Wt + C * C;              // [128][XP]   plain x tile
    float*  s_bp = X + C * XP;              // [128]
    float*  s_gp = s_bp + C;                // [128]
    float*  s_bt = s_gp + C;                // [128]
    float2* red  = (float2*)(s_bt + C);     // [2][80] (sum, sumsq)

    const int tid  = threadIdx.x;
    const int bo   = blockIdx.x / NTILE;
    const int tile = blockIdx.x % NTILE;
    const float* xb = x   + (size_t)bo * C * S + tile * TS;
    float*       ob = out + (size_t)bo * C * S + tile * TS;

    // ---- smem fill ----
    {
        const float4* src = (const float4*)Wt_g;
        float4* dst = (float4*)Wt;
        #pragma unroll 4
        for (int i = tid; i < C * C / 4; i += THREADS) dst[i] = src[i];
    }
    if (tid < C) {
        s_bp[tid] = bp[tid];
        s_gp[tid] = gp[tid];
        s_bt[tid] = betap[tid];
    }
    #pragma unroll 5
    for (int t = tid; t < C * (TS / 4); t += THREADS) {
        int c = t / (TS / 4);
        int q = t % (TS / 4);
        *(float4*)(X + c * XP + q * 4) =
            *(const float4*)(xb + (size_t)c * S + q * 4);
    }
    __syncthreads();

    // ---- mapping ----
    // warp w: jh = w&1 (j half), sgp = w>>1.  lane = 16*h + l.
    // j = jh*64 + l*4 .. +3   (half-warps share W reads)
    // s = sgp*20 + h*10 .. +9 (half-warps own different s groups)
    const int warp = tid >> 5;
    const int lane = tid & 31;
    const int h    = lane >> 4;
    const int l    = lane & 15;
    const int jh   = warp & 1;
    const int j0   = jh * 64 + l * 4;
    const int s0   = (warp >> 1) * 20 + h * 10;

    const float* wrow = Wt + j0;
    const float* xrow = X + s0;

    ull acc[4][5];
    #pragma unroll
    for (int m = 0; m < 4; m++)
        #pragma unroll
        for (int n = 0; n < 5; n++) acc[m][n] = 0ull;

    #pragma unroll 4
    for (int k = 0; k < C; k++) {
        float4 a = *(const float4*)(wrow + k * C);
        ull A0 = pk2(a.x, a.x);
        ull A1 = pk2(a.y, a.y);
        ull A2 = pk2(a.z, a.z);
        ull A3 = pk2(a.w, a.w);
        const ull* bq = (const ull*)(xrow + k * XP);   // 8B-aligned (s0 even)
        ull b0 = bq[0], b1 = bq[1], b2 = bq[2], b3 = bq[3], b4 = bq[4];

        fma2(acc[0][0], A0, b0); fma2(acc[0][1], A0, b1); fma2(acc[0][2], A0, b2);
        fma2(acc[0][3], A0, b3); fma2(acc[0][4], A0, b4);
        fma2(acc[1][0], A1, b0); fma2(acc[1][1], A1, b1); fma2(acc[1][2], A1, b2);
        fma2(acc[1][3], A1, b3); fma2(acc[1][4], A1, b4);
        fma2(acc[2][0], A2, b0); fma2(acc[2][1], A2, b1); fma2(acc[2][2], A2, b2);
        fma2(acc[2][3], A2, b3); fma2(acc[2][4], A2, b4);
        fma2(acc[3][0], A3, b0); fma2(acc[3][1], A3, b1); fma2(acc[3][2], A3, b2);
        fma2(acc[3][3], A3, b3); fma2(acc[3][4], A3, b4);
    }

    // ---- epilogue: +bias, LayerNorm over j (64 intra-warp + 2 warps via smem) ----
    float yv[4][10];
    #pragma unroll
    for (int m = 0; m < 4; m++) {
        float bj = s_bp[j0 + m];
        #pragma unroll
        for (int n = 0; n < 5; n++) {
            float2 v = up2(acc[m][n]);
            yv[m][2 * n]     = v.x + bj;
            yv[m][2 * n + 1] = v.y + bj;
        }
    }

    float sv[10], sq[10];
    #pragma unroll
    for (int n = 0; n < 10; n++) {
        float a = 0.f, b = 0.f;
        #pragma unroll
        for (int m = 0; m < 4; m++) {
            float v = yv[m][n];
            a += v;
            b = fmaf(v, v, b);
        }
        // butterfly over the 16 lanes of this half-warp (xor offsets < 16)
        #pragma unroll
        for (int off = 8; off > 0; off >>= 1) {
            a += __shfl_xor_sync(0xffffffffu, a, off);
            b += __shfl_xor_sync(0xffffffffu, b, off);
        }
        sv[n] = a;
        sq[n] = b;
    }
    if (l == 0) {
        #pragma unroll
        for (int n = 0; n < 10; n++)
            red[jh * TS + s0 + n] = make_float2(sv[n], sq[n]);
    }
    __syncthreads();

    float mu[10], rs[10];
    #pragma unroll
    for (int n = 0; n < 10; n++) {
        float2 r0 = red[s0 + n];
        float2 r1 = red[TS + s0 + n];
        float m_  = (r0.x + r1.x) * (1.0f / 128.0f);
        float var = (r0.y + r1.y) * (1.0f / 128.0f) - m_ * m_;
        mu[n] = m_;
        rs[n] = rsqrtf(var + 1e-5f);
    }

    #pragma unroll
    for (int m = 0; m < 4; m++) {
        int j = j0 + m;
        float g  = s_gp[j];
        float bb = s_bt[j];
        const float* xr = X + j * XP + s0;
        float* orow = ob + (size_t)j * S + s0;
        #pragma unroll
        for (int n = 0; n < 5; n++) {
            float2 o;
            o.x = (yv[m][2*n]   - mu[2*n])   * rs[2*n]   * g + bb + xr[2*n];
            o.y = (yv[m][2*n+1] - mu[2*n+1]) * rs[2*n+1] * g + bb + xr[2*n+1];
            *(float2*)(orow + 2 * n) = o;
        }
    }
}

extern "C" void kernel_launch(void* const* d_in, const int* in_sizes, int n_in,
                              void* d_out, int out_size) {
    // metadata order: x, Wq, bq, gq, betaq, Wk, bk, gk, betak, Wp, bp, gp, betap
    const float* x     = (const float*)d_in[0];
    const float* Wp    = (const float*)d_in[9];
    const float* bp    = (const float*)d_in[10];
    const float* gp    = (const float*)d_in[11];
    const float* betap = (const float*)d_in[12];
    float* out = (float*)d_out;

    const int BO = in_sizes[0] / (C * S);   // 1024
    const size_t smem =
        (size_t)(C * C + C * XP + 3 * C + 2 * 2 * TS) * sizeof(float);

    cudaFuncSetAttribute(ca_kernel,
                         cudaFuncAttributeMaxDynamicSharedMemorySize,
                         (int)smem);

    wt_kernel<<<C * C / 256, 256>>>(Wp);
    ca_kernel<<<BO * NTILE, THREADS, smem>>>(x, bp, gp, betap, out);
}

// round 5
// speedup vs baseline: 2.8269x; 1.6481x over previous
#include <cuda_runtime.h>
#include <cuda_bf16.h>
#include <cstdint>

// channel_attention collapses to: out = LN_c(Wp @ x + bp)*gp + betap + x
// (softmax row-sum == 1 makes the q/k/attention branch an identity).
//
// HMMA path (tcgen05 unavailable: harness targets sm_103 family, not sm_103a):
// D[j][s] = sum_c W[j][c] * x[c][s] via mma.sync.m16n8k16 bf16->fp32,
// 3-term bf16 split for fp32 accuracy. Block = one (b,o) x 80-s tile,
// 10 warps = 5 s-strips x 2 j-halves. Epilogue: LN over j + residual.

#define C        128
#define S        400
#define TS       80
#define NTILE    5
#define THREADS  320
#define WPITCH   136          // bf16 elems per W row (pad: conflict-free ldsm)
#define XPITCH   88           // bf16 elems per X row

// smem byte offsets
#define SM_WH    0
#define SM_WL    (SM_WH + C * WPITCH * 2)     // 34816
#define SM_XH    (SM_WL + C * WPITCH * 2)     // 69632
#define SM_XL    (SM_XH + C * XPITCH * 2)     // 92160
#define SM_BP    (SM_XL + C * XPITCH * 2)     // 114688
#define SM_GP    (SM_BP + 512)
#define SM_BT    (SM_GP + 512)
#define SM_RED   (SM_BT + 512)                // float2[2][80]
#define SM_TOTAL (SM_RED + 1280)              // 117504 B

__device__ __align__(16) __nv_bfloat16 Whp[C * WPITCH];
__device__ __align__(16) __nv_bfloat16 Wlp[C * WPITCH];

__device__ __forceinline__ uint32_t smem_u32(const void* p) {
    uint32_t a;
    asm("{ .reg .u64 t; cvta.to.shared.u64 t, %1; cvt.u32.u64 %0, t; }"
        : "=r"(a) : "l"(p));
    return a;
}
__device__ __forceinline__ void ldsm4(uint32_t r[4], uint32_t addr) {
    asm volatile("ldmatrix.sync.aligned.m8n8.x4.shared.b16 {%0,%1,%2,%3}, [%4];"
                 : "=r"(r[0]), "=r"(r[1]), "=r"(r[2]), "=r"(r[3]) : "r"(addr));
}
__device__ __forceinline__ void ldsm4t(uint32_t r[4], uint32_t addr) {
    asm volatile("ldmatrix.sync.aligned.m8n8.x4.trans.shared.b16 {%0,%1,%2,%3}, [%4];"
                 : "=r"(r[0]), "=r"(r[1]), "=r"(r[2]), "=r"(r[3]) : "r"(addr));
}
__device__ __forceinline__ void mma16816(float d[4], const uint32_t a[4],
                                         uint32_t b0, uint32_t b1) {
    asm volatile(
        "mma.sync.aligned.m16n8k16.row.col.f32.bf16.bf16.f32 "
        "{%0,%1,%2,%3}, {%4,%5,%6,%7}, {%8,%9}, {%0,%1,%2,%3};"
        : "+f"(d[0]), "+f"(d[1]), "+f"(d[2]), "+f"(d[3])
        : "r"(a[0]), "r"(a[1]), "r"(a[2]), "r"(a[3]), "r"(b0), "r"(b1));
}

// W -> bf16 hi/lo images, padded row-major [128][WPITCH]
__global__ void wprep(const float* __restrict__ Wp) {
    int idx = blockIdx.x * 256 + threadIdx.x;     // 0 .. 128*136-1
    int j = idx / WPITCH, c = idx % WPITCH;
    float w = (c < C) ? Wp[j * C + c] : 0.0f;
    __nv_bfloat16 h = __float2bfloat16(w);
    __nv_bfloat16 l = __float2bfloat16(w - __bfloat162float(h));
    Whp[idx] = h;
    Wlp[idx] = l;
}

extern __shared__ char smem[];

__global__ __launch_bounds__(THREADS, 1)
void ca_mma(const float* __restrict__ x,
            const float* __restrict__ bp,
            const float* __restrict__ gp,
            const float* __restrict__ betap,
            float* __restrict__ out) {
    const int tid = threadIdx.x;
    const int bo  = blockIdx.x / NTILE;
    const int tb  = (blockIdx.x % NTILE) * TS;     // s tile base

    const float* xg = x   + (size_t)bo * C * S;
    float*       ob = out + (size_t)bo * C * S;

    float* sbp = (float*)(smem + SM_BP);
    float* sgp = (float*)(smem + SM_GP);
    float* sbt = (float*)(smem + SM_BT);
    float2* red = (float2*)(smem + SM_RED);        // [2][80]

    // ---- smem fill ----
    {
        const uint4* sh = (const uint4*)Whp;
        const uint4* sl = (const uint4*)Wlp;
        uint4* dh = (uint4*)(smem + SM_WH);
        uint4* dl = (uint4*)(smem + SM_WL);
        #pragma unroll 4
        for (int i = tid; i < C * WPITCH * 2 / 16; i += THREADS) {
            dh[i] = sh[i];
            dl[i] = sl[i];
        }
    }
    if (tid < C) {
        sbp[tid] = bp[tid];
        sgp[tid] = gp[tid];
        sbt[tid] = betap[tid];
    }
    // x tile [128 c][80 s] -> bf16 hi/lo, pitch XPITCH
    {
        __nv_bfloat16* xh = (__nv_bfloat16*)(smem + SM_XH);
        __nv_bfloat16* xl = (__nv_bfloat16*)(smem + SM_XL);
        #pragma unroll 4
        for (int i = tid; i < C * (TS / 4); i += THREADS) {
            int c = i / (TS / 4);
            int q = i % (TS / 4);
            float4 v = *(const float4*)(xg + (size_t)c * S + tb + q * 4);
            __nv_bfloat16 h0 = __float2bfloat16(v.x);
            __nv_bfloat16 h1 = __float2bfloat16(v.y);
            __nv_bfloat16 h2 = __float2bfloat16(v.z);
            __nv_bfloat16 h3 = __float2bfloat16(v.w);
            __nv_bfloat16 l0 = __float2bfloat16(v.x - __bfloat162float(h0));
            __nv_bfloat16 l1 = __float2bfloat16(v.y - __bfloat162float(h1));
            __nv_bfloat16 l2 = __float2bfloat16(v.z - __bfloat162float(h2));
            __nv_bfloat16 l3 = __float2bfloat16(v.w - __bfloat162float(h3));
            int o = c * XPITCH + q * 4;
            xh[o] = h0; xh[o+1] = h1; xh[o+2] = h2; xh[o+3] = h3;
            xl[o] = l0; xl[o+1] = l1; xl[o+2] = l2; xl[o+3] = l3;
        }
    }
    __syncthreads();

    // ---- mapping: warp = (s strip, j half) ----
    const int warp  = tid >> 5;
    const int lane  = tid & 31;
    const int strip = warp % 5;          // 16-s strip within tile
    const int jhalf = warp / 5;          // 0 / 1
    const int jbase = jhalf * 64;
    const int sb    = strip * 16;        // s offset within tile
    const int g     = lane >> 2;         // fragment row group
    const int t     = lane & 3;          // fragment col group

    // ldmatrix per-lane addresses (x4 grouping: rows lr, col half lc)
    const int lr = lane & 15;
    const int lc = (lane >> 4) << 3;
    const uint32_t s0 = smem_u32(smem);
    const uint32_t aWh = s0 + SM_WH + (uint32_t)(((jbase + lr) * WPITCH + lc) * 2);
    const uint32_t aWl = aWh + (SM_WL - SM_WH);
    const uint32_t aXh = s0 + SM_XH + (uint32_t)((lr * XPITCH + sb + lc) * 2);
    const uint32_t aXl = aXh + (SM_XL - SM_XH);

    float d[4][2][4];
    #pragma unroll
    for (int mt = 0; mt < 4; mt++)
        #pragma unroll
        for (int nt = 0; nt < 2; nt++)
            #pragma unroll
            for (int i = 0; i < 4; i++) d[mt][nt][i] = 0.0f;

    #pragma unroll
    for (int ks = 0; ks < 8; ks++) {
        uint32_t bh[4], bl[4];
        ldsm4t(bh, aXh + ks * (16 * XPITCH * 2));
        ldsm4t(bl, aXl + ks * (16 * XPITCH * 2));
        uint32_t ah[4][4], al[4][4];
        #pragma unroll
        for (int mt = 0; mt < 4; mt++) {
            ldsm4(ah[mt], aWh + mt * (16 * WPITCH * 2) + ks * 32);
            ldsm4(al[mt], aWl + mt * (16 * WPITCH * 2) + ks * 32);
        }
        #pragma unroll
        for (int mt = 0; mt < 4; mt++) {
            mma16816(d[mt][0], ah[mt], bh[0], bh[1]);
            mma16816(d[mt][1], ah[mt], bh[2], bh[3]);
            mma16816(d[mt][0], al[mt], bh[0], bh[1]);
            mma16816(d[mt][1], al[mt], bh[2], bh[3]);
            mma16816(d[mt][0], ah[mt], bl[0], bl[1]);
            mma16816(d[mt][1], ah[mt], bl[2], bl[3]);
        }
    }

    // ---- epilogue: +bias, LN stats over j (intra-warp + 2-half smem) ----
    float sum[2][2] = {{0.f, 0.f}, {0.f, 0.f}};
    float sq[2][2]  = {{0.f, 0.f}, {0.f, 0.f}};
    #pragma unroll
    for (int mt = 0; mt < 4; mt++) {
        int j0 = jbase + mt * 16 + g;
        float b0v = sbp[j0], b1v = sbp[j0 + 8];
        #pragma unroll
        for (int nt = 0; nt < 2; nt++) {
            d[mt][nt][0] += b0v;
            d[mt][nt][1] += b0v;
            d[mt][nt][2] += b1v;
            d[mt][nt][3] += b1v;
            sum[nt][0] += d[mt][nt][0] + d[mt][nt][2];
            sum[nt][1] += d[mt][nt][1] + d[mt][nt][3];
            sq[nt][0] = fmaf(d[mt][nt][0], d[mt][nt][0],
                        fmaf(d[mt][nt][2], d[mt][nt][2], sq[nt][0]));
            sq[nt][1] = fmaf(d[mt][nt][1], d[mt][nt][1],
                        fmaf(d[mt][nt][3], d[mt][nt][3], sq[nt][1]));
        }
    }
    #pragma unroll
    for (int off = 4; off <= 16; off <<= 1) {
        #pragma unroll
        for (int nt = 0; nt < 2; nt++) {
            #pragma unroll
            for (int p = 0; p < 2; p++) {
                sum[nt][p] += __shfl_xor_sync(0xffffffffu, sum[nt][p], off);
                sq[nt][p]  += __shfl_xor_sync(0xffffffffu, sq[nt][p],  off);
            }
        }
    }
    if (lane < 4) {   // g == 0, lane == t
        #pragma unroll
        for (int nt = 0; nt < 2; nt++)
            #pragma unroll
            for (int p = 0; p < 2; p++)
                red[jhalf * TS + sb + nt * 8 + 2 * t + p] =
                    make_float2(sum[nt][p], sq[nt][p]);
    }
    __syncthreads();

    float mu[2][2], rs[2][2];
    #pragma unroll
    for (int nt = 0; nt < 2; nt++) {
        #pragma unroll
        for (int p = 0; p < 2; p++) {
            int col = sb + nt * 8 + 2 * t + p;
            float2 r0 = red[col];
            float2 r1 = red[TS + col];
            float m_  = (r0.x + r1.x) * (1.0f / 128.0f);
            float var = (r0.y + r1.y) * (1.0f / 128.0f) - m_ * m_;
            mu[nt][p] = m_;
            rs[nt][p] = rsqrtf(var + 1e-5f);
        }
    }

    // ---- apply LN + residual, store ----
    #pragma unroll
    for (int mt = 0; mt < 4; mt++) {
        int j0 = jbase + mt * 16 + g;
        int j1 = j0 + 8;
        float g0 = sgp[j0], e0 = sbt[j0];
        float g1 = sgp[j1], e1 = sbt[j1];
        #pragma unroll
        for (int nt = 0; nt < 2; nt++) {
            int sg = tb + sb + nt * 8 + 2 * t;
            const float* xr0 = xg + (size_t)j0 * S + sg;
            const float* xr1 = xg + (size_t)j1 * S + sg;
            float2 x0 = *(const float2*)xr0;
            float2 x1 = *(const float2*)xr1;
            float2 o0, o1;
            o0.x = (d[mt][nt][0] - mu[nt][0]) * rs[nt][0] * g0 + e0 + x0.x;
            o0.y = (d[mt][nt][1] - mu[nt][1]) * rs[nt][1] * g0 + e0 + x0.y;
            o1.x = (d[mt][nt][2] - mu[nt][0]) * rs[nt][0] * g1 + e1 + x1.x;
            o1.y = (d[mt][nt][3] - mu[nt][1]) * rs[nt][1] * g1 + e1 + x1.y;
            *(float2*)(ob + (size_t)j0 * S + sg) = o0;
            *(float2*)(ob + (size_t)j1 * S + sg) = o1;
        }
    }
}

extern "C" void kernel_launch(void* const* d_in, const int* in_sizes, int n_in,
                              void* d_out, int out_size) {
    // metadata order: x, Wq, bq, gq, betaq, Wk, bk, gk, betak, Wp, bp, gp, betap
    const float* x     = (const float*)d_in[0];
    const float* Wp    = (const float*)d_in[9];
    const float* bp    = (const float*)d_in[10];
    const float* gp    = (const float*)d_in[11];
    const float* betap = (const float*)d_in[12];
    float* out = (float*)d_out;

    const int BO = in_sizes[0] / (C * S);   // 1024

    cudaFuncSetAttribute(ca_mma, cudaFuncAttributeMaxDynamicSharedMemorySize,
                         SM_TOTAL);

    wprep<<<(C * WPITCH) / 256, 256>>>(Wp);
    ca_mma<<<BO * NTILE, THREADS, SM_TOTAL>>>(x, bp, gp, betap, out);
}

// round 6
// speedup vs baseline: 4.0256x; 1.4240x over previous
#include <cuda_runtime.h>
#include <cuda_bf16.h>
#include <cstdint>

// channel_attention collapses to: out = LN_c(Wp @ x + bp)*gp + betap + x
// (softmax row-sum == 1 makes the q/k/attention branch an identity).
//
// HMMA m16n8k16 bf16 3-term-split GEMM (fp32 accuracy). One block per (b,o),
// looping over 5 s-tiles of 80 with register-prefetch double-buffered X;
// W loaded into smem once per block; residual x reconstructed from the bf16
// hi+lo split tile (no second global read of x).

#define C        128
#define S        400
#define TS       80
#define NTILES   5
#define THREADS  320
#define WPITCH   136
#define XPITCH   88

#define SM_WH    0
#define SM_WL    (SM_WH + C * WPITCH * 2)          // 34816
#define SM_XH0   (SM_WL + C * WPITCH * 2)          // 69632
#define SM_XL0   (SM_XH0 + C * XPITCH * 2)         // 92160
#define SM_XH1   (SM_XL0 + C * XPITCH * 2)         // 114688
#define SM_XL1   (SM_XH1 + C * XPITCH * 2)         // 137216
#define SM_BP    (SM_XL1 + C * XPITCH * 2)         // 159744
#define SM_GP    (SM_BP + 512)
#define SM_BT    (SM_GP + 512)
#define SM_RED   (SM_BT + 512)                     // float2[2][80]
#define SM_TOTAL (SM_RED + 1280)                   // 162560 B

__device__ __align__(16) __nv_bfloat16 Whp[C * WPITCH];
__device__ __align__(16) __nv_bfloat16 Wlp[C * WPITCH];

__device__ __forceinline__ uint32_t smem_u32(const void* p) {
    uint32_t a;
    asm("{ .reg .u64 t; cvta.to.shared.u64 t, %1; cvt.u32.u64 %0, t; }"
        : "=r"(a) : "l"(p));
    return a;
}
__device__ __forceinline__ void ldsm4(uint32_t r[4], uint32_t addr) {
    asm volatile("ldmatrix.sync.aligned.m8n8.x4.shared.b16 {%0,%1,%2,%3}, [%4];"
                 : "=r"(r[0]), "=r"(r[1]), "=r"(r[2]), "=r"(r[3]) : "r"(addr));
}
__device__ __forceinline__ void ldsm4t(uint32_t r[4], uint32_t addr) {
    asm volatile("ldmatrix.sync.aligned.m8n8.x4.trans.shared.b16 {%0,%1,%2,%3}, [%4];"
                 : "=r"(r[0]), "=r"(r[1]), "=r"(r[2]), "=r"(r[3]) : "r"(addr));
}
__device__ __forceinline__ void mma16816(float d[4], const uint32_t a[4],
                                         uint32_t b0, uint32_t b1) {
    asm volatile(
        "mma.sync.aligned.m16n8k16.row.col.f32.bf16.bf16.f32 "
        "{%0,%1,%2,%3}, {%4,%5,%6,%7}, {%8,%9}, {%0,%1,%2,%3};"
        : "+f"(d[0]), "+f"(d[1]), "+f"(d[2]), "+f"(d[3])
        : "r"(a[0]), "r"(a[1]), "r"(a[2]), "r"(a[3]), "r"(b0), "r"(b1));
}
__device__ __forceinline__ uint32_t pkhl(float a, float b, uint32_t& lo) {
    __nv_bfloat16 ha = __float2bfloat16(a);
    __nv_bfloat16 hb = __float2bfloat16(b);
    __nv_bfloat162 L = __halves2bfloat162(
        __float2bfloat16(a - __bfloat162float(ha)),
        __float2bfloat16(b - __bfloat162float(hb)));
    __nv_bfloat162 H = __halves2bfloat162(ha, hb);
    lo = *reinterpret_cast<uint32_t*>(&L);
    return *reinterpret_cast<uint32_t*>(&H);
}

__global__ void wprep(const float* __restrict__ Wp) {
    int idx = blockIdx.x * 256 + threadIdx.x;
    int j = idx / WPITCH, c = idx % WPITCH;
    float w = (c < C) ? Wp[j * C + c] : 0.0f;
    __nv_bfloat16 h = __float2bfloat16(w);
    Whp[idx] = h;
    Wlp[idx] = __float2bfloat16(w - __bfloat162float(h));
}

extern __shared__ char smem[];

__global__ __launch_bounds__(THREADS, 1)
void ca_mma(const float* __restrict__ x,
            const float* __restrict__ bp,
            const float* __restrict__ gp,
            const float* __restrict__ betap,
            float* __restrict__ out) {
    const int tid = threadIdx.x;
    const int bo  = blockIdx.x;
    const float* xg = x   + (size_t)bo * C * S;
    float*       ob = out + (size_t)bo * C * S;

    float* sbp = (float*)(smem + SM_BP);
    float* sgp = (float*)(smem + SM_GP);
    float* sbt = (float*)(smem + SM_BT);
    float2* red = (float2*)(smem + SM_RED);

    // ---- one-time fills: W images + bias ----
    {
        const uint4* sh = (const uint4*)Whp;
        const uint4* sl = (const uint4*)Wlp;
        uint4* dh = (uint4*)(smem + SM_WH);
        uint4* dl = (uint4*)(smem + SM_WL);
        #pragma unroll 4
        for (int i = tid; i < C * WPITCH * 2 / 16; i += THREADS) {
            dh[i] = sh[i];
            dl[i] = sl[i];
        }
    }
    if (tid < C) {
        sbp[tid] = bp[tid];
        sgp[tid] = gp[tid];
        sbt[tid] = betap[tid];
    }

    // ---- per-thread load map: 8 chunks of float4 over [128c][80s] ----
    int cc[8], qq[8];
    #pragma unroll
    for (int k = 0; k < 8; k++) {
        int idx = tid + k * THREADS;
        cc[k] = idx / 20;            // c row
        qq[k] = (idx % 20) * 4;      // s offset (float4)
    }

    // ---- warp mapping (same as round 5) ----
    const int warp  = tid >> 5;
    const int lane  = tid & 31;
    const int strip = warp % 5;
    const int jhalf = warp / 5;
    const int jbase = jhalf * 64;
    const int sb    = strip * 16;
    const int g     = lane >> 2;
    const int t4    = lane & 3;
    const int lr    = lane & 15;
    const int lc    = (lane >> 4) << 3;
    const uint32_t s0 = smem_u32(smem);
    const uint32_t aWh = s0 + SM_WH + (uint32_t)(((jbase + lr) * WPITCH + lc) * 2);
    const uint32_t aWl = aWh + (SM_WL - SM_WH);
    const uint32_t xrel = (uint32_t)((lr * XPITCH + sb + lc) * 2);

    // ---- prefetch tile 0 ----
    float4 pre[8];
    #pragma unroll
    for (int k = 0; k < 8; k++)
        pre[k] = *(const float4*)(xg + (size_t)cc[k] * S + qq[k]);

    for (int t = 0; t < NTILES; t++) {
        const int b  = t & 1;
        const uint32_t xhb = b ? SM_XH1 : SM_XH0;
        const uint32_t xlb = b ? SM_XL1 : SM_XL0;
        __nv_bfloat16* xh = (__nv_bfloat16*)(smem + xhb);
        __nv_bfloat16* xl = (__nv_bfloat16*)(smem + xlb);

        __syncthreads();   // buffer b free (its readers finished 2 iters ago)

        // convert prefetched regs -> bf16 hi/lo smem
        #pragma unroll
        for (int k = 0; k < 8; k++) {
            uint32_t l01, l23;
            uint32_t h01 = pkhl(pre[k].x, pre[k].y, l01);
            uint32_t h23 = pkhl(pre[k].z, pre[k].w, l23);
            int o = cc[k] * XPITCH + qq[k];
            *(uint2*)(xh + o) = make_uint2(h01, h23);
            *(uint2*)(xl + o) = make_uint2(l01, l23);
        }
        // prefetch next tile
        if (t + 1 < NTILES) {
            const float* nx = xg + (t + 1) * TS;
            #pragma unroll
            for (int k = 0; k < 8; k++)
                pre[k] = *(const float4*)(nx + (size_t)cc[k] * S + qq[k]);
        }
        __syncthreads();

        // ---- MMA ----
        const uint32_t aXh = s0 + xhb + xrel;
        const uint32_t aXl = s0 + xlb + xrel;

        float d[4][2][4];
        #pragma unroll
        for (int mt = 0; mt < 4; mt++)
            #pragma unroll
            for (int nt = 0; nt < 2; nt++)
                #pragma unroll
                for (int i = 0; i < 4; i++) d[mt][nt][i] = 0.0f;

        #pragma unroll
        for (int ks = 0; ks < 8; ks++) {
            uint32_t bh[4], bl[4];
            ldsm4t(bh, aXh + ks * (16 * XPITCH * 2));
            ldsm4t(bl, aXl + ks * (16 * XPITCH * 2));
            #pragma unroll
            for (int mt = 0; mt < 4; mt++) {
                uint32_t ah[4], al[4];
                ldsm4(ah, aWh + mt * (16 * WPITCH * 2) + ks * 32);
                ldsm4(al, aWl + mt * (16 * WPITCH * 2) + ks * 32);
                mma16816(d[mt][0], ah, bh[0], bh[1]);
                mma16816(d[mt][1], ah, bh[2], bh[3]);
                mma16816(d[mt][0], al, bh[0], bh[1]);
                mma16816(d[mt][1], al, bh[2], bh[3]);
                mma16816(d[mt][0], ah, bl[0], bl[1]);
                mma16816(d[mt][1], ah, bl[2], bl[3]);
            }
        }

        // ---- epilogue: +bias, LN stats over j ----
        float sum[2][2] = {{0.f, 0.f}, {0.f, 0.f}};
        float sq[2][2]  = {{0.f, 0.f}, {0.f, 0.f}};
        #pragma unroll
        for (int mt = 0; mt < 4; mt++) {
            int j0 = jbase + mt * 16 + g;
            float b0v = sbp[j0], b1v = sbp[j0 + 8];
            #pragma unroll
            for (int nt = 0; nt < 2; nt++) {
                d[mt][nt][0] += b0v;
                d[mt][nt][1] += b0v;
                d[mt][nt][2] += b1v;
                d[mt][nt][3] += b1v;
                sum[nt][0] += d[mt][nt][0] + d[mt][nt][2];
                sum[nt][1] += d[mt][nt][1] + d[mt][nt][3];
                sq[nt][0] = fmaf(d[mt][nt][0], d[mt][nt][0],
                            fmaf(d[mt][nt][2], d[mt][nt][2], sq[nt][0]));
                sq[nt][1] = fmaf(d[mt][nt][1], d[mt][nt][1],
                            fmaf(d[mt][nt][3], d[mt][nt][3], sq[nt][1]));
            }
        }
        #pragma unroll
        for (int off = 4; off <= 16; off <<= 1) {
            #pragma unroll
            for (int nt = 0; nt < 2; nt++) {
                #pragma unroll
                for (int p = 0; p < 2; p++) {
                    sum[nt][p] += __shfl_xor_sync(0xffffffffu, sum[nt][p], off);
                    sq[nt][p]  += __shfl_xor_sync(0xffffffffu, sq[nt][p],  off);
                }
            }
        }
        if (lane < 4) {
            #pragma unroll
            for (int nt = 0; nt < 2; nt++)
                #pragma unroll
                for (int p = 0; p < 2; p++)
                    red[jhalf * TS + sb + nt * 8 + 2 * t4 + p] =
                        make_float2(sum[nt][p], sq[nt][p]);
        }
        __syncthreads();

        float mu[2][2], rs[2][2];
        #pragma unroll
        for (int nt = 0; nt < 2; nt++) {
            #pragma unroll
            for (int p = 0; p < 2; p++) {
                int col = sb + nt * 8 + 2 * t4 + p;
                float2 r0 = red[col];
                float2 r1 = red[TS + col];
                float m_  = (r0.x + r1.x) * (1.0f / 128.0f);
                float var = (r0.y + r1.y) * (1.0f / 128.0f) - m_ * m_;
                mu[nt][p] = m_;
                rs[nt][p] = rsqrtf(var + 1e-5f);
            }
        }

        // ---- apply LN + residual (x reconstructed = hi + lo), store ----
        const int tb = t * TS;
        #pragma unroll
        for (int mt = 0; mt < 4; mt++) {
            int j0 = jbase + mt * 16 + g;
            int j1 = j0 + 8;
            float g0 = sgp[j0], e0 = sbt[j0];
            float g1 = sgp[j1], e1 = sbt[j1];
            #pragma unroll
            for (int nt = 0; nt < 2; nt++) {
                int sl = sb + nt * 8 + 2 * t4;     // local s (even)
                __nv_bfloat162 h0 = *(__nv_bfloat162*)(xh + j0 * XPITCH + sl);
                __nv_bfloat162 l0 = *(__nv_bfloat162*)(xl + j0 * XPITCH + sl);
                __nv_bfloat162 h1 = *(__nv_bfloat162*)(xh + j1 * XPITCH + sl);
                __nv_bfloat162 l1 = *(__nv_bfloat162*)(xl + j1 * XPITCH + sl);
                float2 o0, o1;
                o0.x = (d[mt][nt][0] - mu[nt][0]) * rs[nt][0] * g0 + e0 +
                       __bfloat162float(h0.x) + __bfloat162float(l0.x);
                o0.y = (d[mt][nt][1] - mu[nt][1]) * rs[nt][1] * g0 + e0 +
                       __bfloat162float(h0.y) + __bfloat162float(l0.y);
                o1.x = (d[mt][nt][2] - mu[nt][0]) * rs[nt][0] * g1 + e1 +
                       __bfloat162float(h1.x) + __bfloat162float(l1.x);
                o1.y = (d[mt][nt][3] - mu[nt][1]) * rs[nt][1] * g1 + e1 +
                       __bfloat162float(h1.y) + __bfloat162float(l1.y);
                *(float2*)(ob + (size_t)j0 * S + tb + sl) = o0;
                *(float2*)(ob + (size_t)j1 * S + tb + sl) = o1;
            }
        }
    }
}

extern "C" void kernel_launch(void* const* d_in, const int* in_sizes, int n_in,
                              void* d_out, int out_size) {
    // metadata order: x, Wq, bq, gq, betaq, Wk, bk, gk, betak, Wp, bp, gp, betap
    const float* x     = (const float*)d_in[0];
    const float* Wp    = (const float*)d_in[9];
    const float* bp    = (const float*)d_in[10];
    const float* gp    = (const float*)d_in[11];
    const float* betap = (const float*)d_in[12];
    float* out = (float*)d_out;

    const int BO = in_sizes[0] / (C * S);   // 1024

    cudaFuncSetAttribute(ca_mma, cudaFuncAttributeMaxDynamicSharedMemorySize,
                         SM_TOTAL);

    wprep<<<(C * WPITCH) / 256, 256>>>(Wp);
    ca_mma<<<BO, THREADS, SM_TOTAL>>>(x, bp, gp, betap, out);
}